// round 1
// baseline (speedup 1.0000x reference)
#include <cuda_runtime.h>
#include <cstdint>

// Problem constants (fixed shapes from the reference)
#define B_SZ    2
#define GQ      32
#define HDIM    128
#define NH      8
#define DK      16
#define S_LEN   4096
#define STILE   16
#define NTHREADS 256

// SMEM layout (floats)
#define Q_STRIDE   (DK*STILE + 4)          // 260, padded, 16B-aligned rows
#define Q_SIZE     (GQ * Q_STRIDE)         // 8320
#define KV_SIZE    (GQ * DK * STILE)       // 8192
#define SUM_STRIDE (GQ*STILE + 2)          // 514, padded, 8B-aligned
#define SUM_SIZE   (GQ * SUM_STRIDE)       // 16448
#define SM_Q    0
#define SM_K    (SM_Q + Q_SIZE)            // 8320
#define SM_V    (SM_K + KV_SIZE)           // 16512
#define SM_L    (SM_V + KV_SIZE)           // 24704
#define SM_A    (SM_L + SUM_SIZE)          // 41152
#define SM_TOTAL_FLOATS (SM_A + SUM_SIZE)  // 57600
#define SM_BYTES (SM_TOTAL_FLOATS * 4)     // 230400  (<= 232448 max)

typedef unsigned long long u64;

// ---- packed f32x2 helpers (Blackwell sm_100+) ----
__device__ __forceinline__ u64 pk2(float lo, float hi) {
    u64 r; asm("mov.b64 %0, {%1, %2};" : "=l"(r) : "f"(lo), "f"(hi)); return r;
}
__device__ __forceinline__ void up2(u64 v, float& lo, float& hi) {
    asm("mov.b64 {%0, %1}, %2;" : "=f"(lo), "=f"(hi) : "l"(v));
}
__device__ __forceinline__ u64 fma2(u64 a, u64 b, u64 c) {
    u64 d; asm("fma.rn.f32x2 %0, %1, %2, %3;" : "=l"(d) : "l"(a), "l"(b), "l"(c)); return d;
}
__device__ __forceinline__ u64 add2(u64 a, u64 b) {
    u64 d; asm("add.rn.f32x2 %0, %1, %2;" : "=l"(d) : "l"(a), "l"(b)); return d;
}
__device__ __forceinline__ u64 mul2(u64 a, u64 b) {
    u64 d; asm("mul.rn.f32x2 %0, %1, %2;" : "=l"(d) : "l"(a), "l"(b)); return d;
}
__device__ __forceinline__ float ex2a(float x) {
    float r; asm("ex2.approx.ftz.f32 %0, %1;" : "=f"(r) : "f"(x)); return r;
}
__device__ __forceinline__ float rcpa(float x) {
    float r; asm("rcp.approx.ftz.f32 %0, %1;" : "=f"(r) : "f"(x)); return r;
}

__global__ void __launch_bounds__(NTHREADS, 1)
sdpa_group_kernel(const float* __restrict__ q, const float* __restrict__ k,
                  const float* __restrict__ v, float* __restrict__ out)
{
    extern __shared__ float sm[];
    float* sQ = sm + SM_Q;
    float* sK = sm + SM_K;
    float* sV = sm + SM_V;
    float* sL = sm + SM_L;
    float* sA = sm + SM_A;

    const int tile = blockIdx.x;
    const int b    = blockIdx.y;
    const int s0   = tile * STILE;
    const int t    = threadIdx.x;
    const int lane = t & 31;
    const int warp = t >> 5;
    const int g    = lane;        // group index (also f index by symmetry)
    const int sp   = warp;        // s-pair: s = 2*sp, 2*sp+1

    // zero the head-sum accumulators (sL and sA are contiguous)
    #pragma unroll 4
    for (int i = t; i < 2 * SUM_SIZE; i += NTHREADS) sL[i] = 0.0f;

    // staging decomposition: thread t handles s-quarter (t&3) of row (t>>2)+64*rr
    const int sq4 = t & 3;
    const int r0  = t >> 2;

    const size_t base_in = (size_t)b * (GQ * HDIM) * S_LEN + (size_t)s0;

    #pragma unroll 1
    for (int h = 0; h < NH; ++h) {
        __syncthreads();   // previous compute done before tiles are overwritten

        // ---- stage Q,K,V head-h tiles: global (s contiguous) -> smem [row][s] ----
        const float* gq = q + base_in + (size_t)h * DK * S_LEN;
        const float* gk = k + base_in + (size_t)h * DK * S_LEN;
        const float* gv = v + base_in + (size_t)h * DK * S_LEN;
        #pragma unroll
        for (int rr = 0; rr < 8; ++rr) {
            int r  = r0 + rr * 64;          // 0..511 = g*16 + d
            int gg = r >> 4, dd = r & 15;
            size_t go = ((size_t)gg * HDIM + dd) * S_LEN + 4 * sq4;
            float4 vq = *(const float4*)(gq + go);
            float4 vk = *(const float4*)(gk + go);
            float4 vv = *(const float4*)(gv + go);
            *(float4*)(sQ + gg * Q_STRIDE + dd * STILE + 4 * sq4) = vq;
            *(float4*)(sK + r * STILE + 4 * sq4) = vk;
            *(float4*)(sV + r * STILE + 4 * sq4) = vv;
        }
        __syncthreads();

        // ---- load q vector (pre-scaled by d_k^-0.5 = 0.25), packed over s-pair ----
        const float* qr = sQ + g * Q_STRIDE + 2 * sp;
        const u64 sc = pk2(0.25f, 0.25f);
        u64 qv[DK];
        #pragma unroll
        for (int d = 0; d < DK; ++d)
            qv[d] = mul2(*(const u64*)(qr + d * STILE), sc);

        // ---- logits[g][f] for 2 s at once: broadcast LDS.64 of K + fma.f32x2 ----
        u64 lg[GQ];
        #pragma unroll
        for (int f = 0; f < GQ; ++f) {
            const float* kr = sK + f * (DK * STILE) + 2 * sp;
            u64 a0 = mul2(qv[0], *(const u64*)(kr));
            u64 a1 = mul2(qv[1], *(const u64*)(kr + STILE));
            #pragma unroll
            for (int d = 2; d < DK; d += 2) {
                a0 = fma2(qv[d],     *(const u64*)(kr + d * STILE),       a0);
                a1 = fma2(qv[d + 1], *(const u64*)(kr + (d + 1) * STILE), a1);
            }
            lg[f] = add2(a0, a1);
        }

        // ---- accumulate logits_sum (CTA-private rows: no races) ----
        float* lrow = sL + g * SUM_STRIDE + 2 * sp;
        #pragma unroll
        for (int f = 0; f < GQ; ++f) {
            u64* p = (u64*)(lrow + f * STILE);
            *p = add2(*p, lg[f]);
        }

        // ---- softmax over f (per s component) ----
        float m0 = -1e30f, m1 = -1e30f;
        #pragma unroll
        for (int f = 0; f < GQ; ++f) {
            float a, bb; up2(lg[f], a, bb);
            m0 = fmaxf(m0, a); m1 = fmaxf(m1, bb);
        }
        const float L2E = 1.4426950408889634f;
        const float c0 = m0 * L2E, c1 = m1 * L2E;
        float sum0 = 0.0f, sum1 = 0.0f;
        #pragma unroll
        for (int f = 0; f < GQ; ++f) {
            float a, bb; up2(lg[f], a, bb);
            float e0 = ex2a(fmaf(a,  L2E, -c0));
            float e1 = ex2a(fmaf(bb, L2E, -c1));
            sum0 += e0; sum1 += e1;
            lg[f] = pk2(e0, e1);
        }
        const u64 rn = pk2(rcpa(sum0), rcpa(sum1));

        // ---- normalize, accumulate attn_sum ----
        float* arow = sA + g * SUM_STRIDE + 2 * sp;
        #pragma unroll
        for (int f = 0; f < GQ; ++f) {
            lg[f] = mul2(lg[f], rn);
            u64* p = (u64*)(arow + f * STILE);
            *p = add2(*p, lg[f]);
        }

        // ---- x[g][d] = sum_f attn[f] * V[f][d], packed over the s-pair ----
        u64 xv[DK];
        {
            const float* vr0 = sV + 2 * sp;
            #pragma unroll
            for (int d = 0; d < DK; ++d)
                xv[d] = mul2(lg[0], *(const u64*)(vr0 + d * STILE));
            #pragma unroll
            for (int f = 1; f < GQ; ++f) {
                const float* vf = sV + f * (DK * STILE) + 2 * sp;
                #pragma unroll
                for (int d = 0; d < DK; ++d)
                    xv[d] = fma2(lg[f], *(const u64*)(vf + d * STILE), xv[d]);
            }
        }

        // ---- store x: out[b][g*128 + h*16 + d][s0 + 2sp .. +1]  (8B stores) ----
        float* xo = out + (((size_t)(b * GQ + g) * HDIM) + (size_t)h * DK) * S_LEN
                        + (size_t)s0 + 2 * sp;
        #pragma unroll
        for (int d = 0; d < DK; ++d)
            *(u64*)(xo + (size_t)d * S_LEN) = xv[d];
    }

    // ---- writeout head means: attn_mean then logits_mean, coalesced over s ----
    __syncthreads();
    const size_t AOFF = (size_t)B_SZ * GQ * HDIM * S_LEN;          // 33554432
    const size_t LOFF = AOFF + (size_t)B_SZ * GQ * GQ * S_LEN;     // 41943040
    const int ss = t & 15;
    #pragma unroll 4
    for (int r = (t >> 4); r < GQ * GQ; r += 16) {
        int gg = r >> 5, ff = r & 31;
        size_t o = ((size_t)(b * GQ + gg) * GQ + ff) * S_LEN + (size_t)s0 + ss;
        int sa = gg * SUM_STRIDE + ff * STILE + ss;
        out[AOFF + o] = sA[sa] * 0.125f;
        out[LOFF + o] = sL[sa] * 0.125f;
    }
}

extern "C" void kernel_launch(void* const* d_in, const int* in_sizes, int n_in,
                              void* d_out, int out_size)
{
    const float* q = (const float*)d_in[0];
    const float* k = (const float*)d_in[1];
    const float* v = (const float*)d_in[2];
    float* out = (float*)d_out;

    cudaFuncSetAttribute(sdpa_group_kernel,
                         cudaFuncAttributeMaxDynamicSharedMemorySize, SM_BYTES);

    dim3 grid(S_LEN / STILE, B_SZ);
    sdpa_group_kernel<<<grid, NTHREADS, SM_BYTES>>>(q, k, v, out);
}

// round 2
// speedup vs baseline: 1.1089x; 1.1089x over previous
#include <cuda_runtime.h>
#include <cstdint>

#define B_SZ  2
#define GQ    32
#define HDIM  128
#define NH    8
#define DK    16
#define SLEN  4096
#define STILE 8
#define NT    128

typedef unsigned long long u64;

// SMEM layout (u64 units):
//  [0, 2048)          sQ   : u64[(d*4+sp)*32 + g]
//  [2048, 4096)       sKV  : shared K then V; float view: [f:32][128 floats]
//                            unit(d2,sp) 16B = {s0*dlo, s1*dlo, s0*dhi, s1*dhi},
//                            swizzled: d2' = d2 ^ (f&7)
//  [4096, 8256)       sumL : u64[g*130 + sp*32 + f]   (logits sum over h)
//  [8256, 12416)      sumA : same layout               (attn sum over h)
#define SQ_U64   0
#define SKV_U64  2048
#define SUML_U64 4096
#define SUMA_U64 8256
#define SM_U64_TOTAL 12416
#define SM_BYTES (SM_U64_TOTAL * 8)   // 99328 B -> 2 CTAs/SM

// ---- packed f32x2 helpers (Blackwell) ----
__device__ __forceinline__ u64 pk2(float lo, float hi) {
    u64 r; asm("mov.b64 %0, {%1, %2};" : "=l"(r) : "f"(lo), "f"(hi)); return r;
}
__device__ __forceinline__ void up2(u64 v, float& lo, float& hi) {
    asm("mov.b64 {%0, %1}, %2;" : "=f"(lo), "=f"(hi) : "l"(v));
}
__device__ __forceinline__ u64 fma2(u64 a, u64 b, u64 c) {
    u64 d; asm("fma.rn.f32x2 %0, %1, %2, %3;" : "=l"(d) : "l"(a), "l"(b), "l"(c)); return d;
}
__device__ __forceinline__ u64 add2(u64 a, u64 b) {
    u64 d; asm("add.rn.f32x2 %0, %1, %2;" : "=l"(d) : "l"(a), "l"(b)); return d;
}
__device__ __forceinline__ u64 mul2(u64 a, u64 b) {
    u64 d; asm("mul.rn.f32x2 %0, %1, %2;" : "=l"(d) : "l"(a), "l"(b)); return d;
}
__device__ __forceinline__ float ex2a(float x) {
    float r; asm("ex2.approx.ftz.f32 %0, %1;" : "=f"(r) : "f"(x)); return r;
}
__device__ __forceinline__ float rcpa(float x) {
    float r; asm("rcp.approx.ftz.f32 %0, %1;" : "=f"(r) : "f"(x)); return r;
}

__global__ void __launch_bounds__(NT, 2)
sdpa_group_kernel(const float* __restrict__ q, const float* __restrict__ k,
                  const float* __restrict__ v, float* __restrict__ out)
{
    extern __shared__ u64 sm[];
    u64*   sQ  = sm + SQ_U64;
    float* sKV = (float*)(sm + SKV_U64);
    u64*   sL  = sm + SUML_U64;
    u64*   sA  = sm + SUMA_U64;

    const int t    = threadIdx.x;
    const int lane = t & 31;
    const int warp = t >> 5;
    const int g    = lane;           // group index (query side); also f for staging rows
    const int sp   = warp;           // s-pair: s = 2sp, 2sp+1 (sp in [0,4))
    const int s0   = blockIdx.x * STILE;
    const int b    = blockIdx.y;

    // zero both accumulator regions (contiguous: sL..end of sA)
    #pragma unroll 4
    for (int i = t; i < 2 * 4160; i += NT) sL[i] = 0ull;

    const size_t base = (size_t)b * (GQ * HDIM) * SLEN + (size_t)s0;

    #pragma unroll 1
    for (int h = 0; h < NH; ++h) {
        __syncthreads();   // prior iteration done with sQ/sKV

        const float* gq = q + base + (size_t)h * DK * SLEN;
        const float* gk = k + base + (size_t)h * DK * SLEN;
        const float* gv = v + base + (size_t)h * DK * SLEN;

        // ---- stage Q: rows (g=lane, d=warp+4i), 8 floats each -> u64[(d*4+sp)*32+g] ----
        #pragma unroll
        for (int i = 0; i < 4; ++i) {
            int d = warp + 4 * i;
            const float* src = gq + ((size_t)lane * HDIM + d) * SLEN;
            float4 a0 = *(const float4*)src;
            float4 a1 = *(const float4*)(src + 4);
            ulonglong2 p0 = *(ulonglong2*)&a0;
            ulonglong2 p1 = *(ulonglong2*)&a1;
            u64* dst = sQ + (size_t)(d * 4) * 32 + lane;
            dst[0]  = p0.x; dst[32] = p0.y; dst[64] = p1.x; dst[96] = p1.y;
        }

        // ---- stage K into sKV (interleaved units), prefetch V into registers ----
        float4 vh[2][4];
        {
            const int sw = (lane & 7);   // swizzle: d2' = d2 ^ sw
            #pragma unroll
            for (int i = 0; i < 2; ++i) {
                int d2 = warp + 4 * i;
                const float* srcK = gk + ((size_t)lane * HDIM + 2 * d2) * SLEN;
                float4 kl0 = *(const float4*)(srcK);
                float4 kl1 = *(const float4*)(srcK + 4);
                float4 kh0 = *(const float4*)(srcK + SLEN);
                float4 kh1 = *(const float4*)(srcK + SLEN + 4);
                const float* srcV = gv + ((size_t)lane * HDIM + 2 * d2) * SLEN;
                vh[i][0] = *(const float4*)(srcV);
                vh[i][1] = *(const float4*)(srcV + 4);
                vh[i][2] = *(const float4*)(srcV + SLEN);
                vh[i][3] = *(const float4*)(srcV + SLEN + 4);

                float* frow = sKV + lane * 128;
                ulonglong2 plo0 = *(ulonglong2*)&kl0, plo1 = *(ulonglong2*)&kl1;
                ulonglong2 phi0 = *(ulonglong2*)&kh0, phi1 = *(ulonglong2*)&kh1;
                int d2s = (d2 ^ sw) * 4;
                *(ulonglong2*)(frow + ((d2s + 0) << 2)) = make_ulonglong2(plo0.x, phi0.x);
                *(ulonglong2*)(frow + ((d2s + 1) << 2)) = make_ulonglong2(plo0.y, phi0.y);
                *(ulonglong2*)(frow + ((d2s + 2) << 2)) = make_ulonglong2(plo1.x, phi1.x);
                *(ulonglong2*)(frow + ((d2s + 3) << 2)) = make_ulonglong2(plo1.y, phi1.y);
            }
        }
        __syncthreads();

        // ---- qv: Q row for (g, s-pair), pre-scaled by dk^-0.5 = 0.25 ----
        u64 qv[DK];
        {
            const u64 sc = pk2(0.25f, 0.25f);
            const u64* qp = sQ + sp * 32 + g;
            #pragma unroll
            for (int d = 0; d < DK; ++d) qv[d] = mul2(qp[d * 128], sc);
        }

        // ---- logits: broadcast LDS.128 (dlo,dhi s-pair) + 2 FMA2, zero repack ----
        u64 lg[GQ];
        #pragma unroll
        for (int f = 0; f < GQ; ++f) {
            const float* frow = sKV + f * 128;
            const int fs = f & 7;
            u64 a0, a1;
            {
                ulonglong2 kk = *(const ulonglong2*)(frow + ((((0 ^ fs) * 4) + sp) << 2));
                a0 = mul2(qv[0], kk.x);
                a1 = mul2(qv[1], kk.y);
            }
            #pragma unroll
            for (int d2 = 1; d2 < 8; ++d2) {
                ulonglong2 kk = *(const ulonglong2*)(frow + ((((d2 ^ fs) * 4) + sp) << 2));
                a0 = fma2(qv[2 * d2],     kk.x, a0);
                a1 = fma2(qv[2 * d2 + 1], kk.y, a1);
            }
            lg[f] = add2(a0, a1);
        }

        // ---- accumulate logits sums (16B RMW) ----
        u64* Lr = sL + g * 130 + sp * 32;
        #pragma unroll
        for (int f = 0; f < GQ; f += 2) {
            ulonglong2* p = (ulonglong2*)(Lr + f);
            ulonglong2 c = *p;
            c.x = add2(c.x, lg[f]);
            c.y = add2(c.y, lg[f + 1]);
            *p = c;
        }

        // ---- softmax over f, per s component ----
        float m0 = -1e30f, m1 = -1e30f;
        #pragma unroll
        for (int f = 0; f < GQ; ++f) {
            float a, bb; up2(lg[f], a, bb);
            m0 = fmaxf(m0, a); m1 = fmaxf(m1, bb);
        }
        const float L2E = 1.4426950408889634f;
        const float c0 = m0 * L2E, c1 = m1 * L2E;
        float sum0 = 0.0f, sum1 = 0.0f;
        #pragma unroll
        for (int f = 0; f < GQ; ++f) {
            float a, bb; up2(lg[f], a, bb);
            float e0 = ex2a(fmaf(a,  L2E, -c0));
            float e1 = ex2a(fmaf(bb, L2E, -c1));
            sum0 += e0; sum1 += e1;
            lg[f] = pk2(e0, e1);
        }
        const u64 rn = pk2(rcpa(sum0), rcpa(sum1));

        // ---- normalize + accumulate attn sums ----
        u64* Ar = sA + g * 130 + sp * 32;
        #pragma unroll
        for (int f = 0; f < GQ; f += 2) {
            lg[f]     = mul2(lg[f],     rn);
            lg[f + 1] = mul2(lg[f + 1], rn);
            ulonglong2* p = (ulonglong2*)(Ar + f);
            ulonglong2 c = *p;
            c.x = add2(c.x, lg[f]);
            c.y = add2(c.y, lg[f + 1]);
            *p = c;
        }

        __syncthreads();   // all warps done reading K from sKV

        // ---- store prefetched V into sKV (same interleaved layout) ----
        {
            const int sw = (lane & 7);
            #pragma unroll
            for (int i = 0; i < 2; ++i) {
                int d2 = warp + 4 * i;
                float* frow = sKV + lane * 128;
                ulonglong2 plo0 = *(ulonglong2*)&vh[i][0], plo1 = *(ulonglong2*)&vh[i][1];
                ulonglong2 phi0 = *(ulonglong2*)&vh[i][2], phi1 = *(ulonglong2*)&vh[i][3];
                int d2s = (d2 ^ sw) * 4;
                *(ulonglong2*)(frow + ((d2s + 0) << 2)) = make_ulonglong2(plo0.x, phi0.x);
                *(ulonglong2*)(frow + ((d2s + 1) << 2)) = make_ulonglong2(plo0.y, phi0.y);
                *(ulonglong2*)(frow + ((d2s + 2) << 2)) = make_ulonglong2(plo1.x, phi1.x);
                *(ulonglong2*)(frow + ((d2s + 3) << 2)) = make_ulonglong2(plo1.y, phi1.y);
            }
        }
        __syncthreads();

        // ---- x[g][d] = sum_f attn[f] * V[f][d] ----
        u64 xv[DK];
        {
            const float* frow0 = sKV; // f = 0
            #pragma unroll
            for (int d2 = 0; d2 < 8; ++d2) {
                ulonglong2 vv = *(const ulonglong2*)(frow0 + (((d2 * 4) + sp) << 2));
                xv[2 * d2]     = mul2(lg[0], vv.x);
                xv[2 * d2 + 1] = mul2(lg[0], vv.y);
            }
            #pragma unroll
            for (int f = 1; f < GQ; ++f) {
                const float* frow = sKV + f * 128;
                const int fs = f & 7;
                #pragma unroll
                for (int d2 = 0; d2 < 8; ++d2) {
                    ulonglong2 vv = *(const ulonglong2*)(frow + ((((d2 ^ fs) * 4) + sp) << 2));
                    xv[2 * d2]     = fma2(lg[f], vv.x, xv[2 * d2]);
                    xv[2 * d2 + 1] = fma2(lg[f], vv.y, xv[2 * d2 + 1]);
                }
            }
        }

        // ---- store x: out[b][g*128 + h*16 + d][s0 + 2sp + {0,1}] ----
        float* xo = out + (((size_t)(b * GQ + g) * HDIM) + (size_t)h * DK) * SLEN
                        + (size_t)s0 + 2 * sp;
        #pragma unroll
        for (int d = 0; d < DK; ++d)
            *(u64*)(xo + (size_t)d * SLEN) = xv[d];
    }

    // ---- writeout head means (x8 -> *0.125) ----
    __syncthreads();
    const size_t AOFF = (size_t)B_SZ * GQ * HDIM * SLEN;       // 33554432
    const size_t LOFF = AOFF + (size_t)B_SZ * GQ * GQ * SLEN;  // 41943040
    const u64 c8 = pk2(0.125f, 0.125f);
    #pragma unroll
    for (int i = 0; i < 8; ++i) {
        int r = t + NT * i;        // 0..1023
        int f  = r & 31;
        int gg = r >> 5;
        const u64* As = sA + gg * 130 + f;
        const u64* Ls = sL + gg * 130 + f;
        size_t o = ((size_t)(b * GQ + gg) * GQ + f) * SLEN + (size_t)s0;
        #pragma unroll
        for (int sp2 = 0; sp2 < 4; ++sp2) {
            *(u64*)(out + AOFF + o + 2 * sp2) = mul2(As[sp2 * 32], c8);
            *(u64*)(out + LOFF + o + 2 * sp2) = mul2(Ls[sp2 * 32], c8);
        }
    }
}

extern "C" void kernel_launch(void* const* d_in, const int* in_sizes, int n_in,
                              void* d_out, int out_size)
{
    const float* q = (const float*)d_in[0];
    const float* k = (const float*)d_in[1];
    const float* v = (const float*)d_in[2];
    float* out = (float*)d_out;

    cudaFuncSetAttribute(sdpa_group_kernel,
                         cudaFuncAttributeMaxDynamicSharedMemorySize, SM_BYTES);

    dim3 grid(SLEN / STILE, B_SZ);
    sdpa_group_kernel<<<grid, NT, SM_BYTES>>>(q, k, v, out);
}

// round 3
// speedup vs baseline: 1.2860x; 1.1597x over previous
#include <cuda_runtime.h>
#include <cstdint>

#define B_SZ  2
#define GQ    32
#define HDIM  128
#define NH    8
#define DK    16
#define SLEN  4096
#define STILE 8
#define NT    128

typedef unsigned long long u64;

// SMEM (u64 units): sQ [0,2048) u64[(d*4+sp)*32+g]
//   sK [2048,4096) float[f][d][s:8]   sV [4096,6144) same
//   sumL [6144,10304) u64[g*130 + sp*32 + f]   sumA [10304,14464)
#define SQ_U64   0
#define SK_U64   2048
#define SV_U64   4096
#define SUML_U64 6144
#define SUMA_U64 10304
#define SM_U64_TOTAL 14464
#define SM_BYTES (SM_U64_TOTAL * 8)   // 115712 B -> 2 CTAs/SM

// ---- packed f32x2 + misc helpers ----
__device__ __forceinline__ u64 pk2(float lo, float hi) {
    u64 r; asm("mov.b64 %0, {%1, %2};" : "=l"(r) : "f"(lo), "f"(hi)); return r;
}
__device__ __forceinline__ void up2(u64 v, float& lo, float& hi) {
    asm("mov.b64 {%0, %1}, %2;" : "=f"(lo), "=f"(hi) : "l"(v));
}
__device__ __forceinline__ u64 fma2(u64 a, u64 b, u64 c) {
    u64 d; asm("fma.rn.f32x2 %0, %1, %2, %3;" : "=l"(d) : "l"(a), "l"(b), "l"(c)); return d;
}
__device__ __forceinline__ u64 add2(u64 a, u64 b) {
    u64 d; asm("add.rn.f32x2 %0, %1, %2;" : "=l"(d) : "l"(a), "l"(b)); return d;
}
__device__ __forceinline__ u64 mul2(u64 a, u64 b) {
    u64 d; asm("mul.rn.f32x2 %0, %1, %2;" : "=l"(d) : "l"(a), "l"(b)); return d;
}
__device__ __forceinline__ float ex2a(float x) {
    float r; asm("ex2.approx.ftz.f32 %0, %1;" : "=f"(r) : "f"(x)); return r;
}
__device__ __forceinline__ float rcpa(float x) {
    float r; asm("rcp.approx.ftz.f32 %0, %1;" : "=f"(r) : "f"(x)); return r;
}
__device__ __forceinline__ void cp_async16(void* dst, const void* src) {
    unsigned sdst = (unsigned)__cvta_generic_to_shared(dst);
    asm volatile("cp.async.cg.shared.global [%0], [%1], 16;" :: "r"(sdst), "l"(src));
}
__device__ __forceinline__ void cp_commit() {
    asm volatile("cp.async.commit_group;" ::: "memory");
}
__device__ __forceinline__ void cp_wait0() {
    asm volatile("cp.async.wait_group 0;" ::: "memory");
}

// stage a 32x16x8-float tile (K or V), global row (g,d) -> smem [g*16+d][s:8]
__device__ __forceinline__ void stage_async(float* dst, const float* src0, int t) {
    #pragma unroll
    for (int i = 0; i < 8; ++i) {
        int c = t + NT * i;        // 16B chunk id, lanes consecutive
        int r = c >> 1;            // row = g*16+d
        const float* src = src0 + ((size_t)(r >> 4) * HDIM + (r & 15)) * SLEN + 4 * (c & 1);
        cp_async16(dst + 4 * c, src);
    }
}

__device__ __forceinline__ void load_q_ldg(ulonglong2* qA, ulonglong2* qB,
                                           const float* gq, int lane, int warp) {
    #pragma unroll
    for (int i = 0; i < 4; ++i) {
        int d = warp + 4 * i;
        const float* src = gq + ((size_t)lane * HDIM + d) * SLEN;
        qA[i] = *(const ulonglong2*)(src);
        qB[i] = *(const ulonglong2*)(src + 4);
    }
}
__device__ __forceinline__ void sts_q(u64* sQ, const ulonglong2* qA, const ulonglong2* qB,
                                      int lane, int warp) {
    #pragma unroll
    for (int i = 0; i < 4; ++i) {
        int d = warp + 4 * i;
        u64* dst = sQ + (size_t)(d * 4) * 32 + lane;
        dst[0] = qA[i].x; dst[32] = qA[i].y; dst[64] = qB[i].x; dst[96] = qB[i].y;
    }
}

__global__ void __launch_bounds__(NT, 2)
sdpa_group_kernel(const float* __restrict__ q, const float* __restrict__ k,
                  const float* __restrict__ v, float* __restrict__ out)
{
    extern __shared__ u64 sm[];
    u64*   sQ = sm + SQ_U64;
    float* sK = (float*)(sm + SK_U64);
    float* sV = (float*)(sm + SV_U64);
    u64*   sL = sm + SUML_U64;
    u64*   sA = sm + SUMA_U64;

    const int t    = threadIdx.x;
    const int lane = t & 31;
    const int warp = t >> 5;
    const int g    = lane;
    const int sp   = warp;                 // s-pair: s = 2sp, 2sp+1
    const int s0   = blockIdx.x * STILE;
    const int b    = blockIdx.y;

    const size_t base = (size_t)b * (GQ * HDIM) * SLEN + (size_t)s0;
    const float L2E = 1.4426950408889634f;

    // ---- prologue: async K(0), LDG Q(0), zero sums, STS Q(0) ----
    stage_async(sK, k + base, t);
    cp_commit();
    ulonglong2 qA[4], qB[4];
    load_q_ldg(qA, qB, q + base, lane, warp);
    #pragma unroll 4
    for (int i = t; i < 8320; i += NT) sL[i] = 0ull;   // sL..sA contiguous
    sts_q(sQ, qA, qB, lane, warp);

    const u64 sc = pk2(0.25f * L2E, 0.25f * L2E);      // dk^-0.5 * log2(e)

    #pragma unroll 1
    for (int h = 0; h < NH; ++h) {
        cp_wait0();              // K(h) arrived (per-thread)
        __syncthreads();         // Q(h) STS + K visible; sV free

        // prefetch V(h) (consumed after next barrier)
        stage_async(sV, v + base + (size_t)h * DK * SLEN, t);
        cp_commit();

        // ---- qv = Q[g, :, s-pair] * scale ----
        u64 qv[DK];
        {
            const u64* qp = sQ + sp * 32 + g;
            #pragma unroll
            for (int d = 0; d < DK; ++d) qv[d] = mul2(qp[d * 128], sc);
        }

        // ---- logits (log2-domain): broadcast LDS.64 + FMA2 ----
        u64 lg[GQ];
        #pragma unroll
        for (int f = 0; f < GQ; ++f) {
            const float* kb = sK + f * 128 + 2 * sp;
            u64 a0 = mul2(qv[0], *(const u64*)(kb));
            u64 a1 = mul2(qv[1], *(const u64*)(kb + 8));
            #pragma unroll
            for (int d = 2; d < DK; d += 2) {
                a0 = fma2(qv[d],     *(const u64*)(kb + 8 * d),     a0);
                a1 = fma2(qv[d + 1], *(const u64*)(kb + 8 * d + 8), a1);
            }
            lg[f] = add2(a0, a1);
        }

        // ---- accumulate logits sums ----
        u64* Lr = sL + g * 130 + sp * 32;
        #pragma unroll
        for (int f = 0; f < GQ; f += 2) {
            ulonglong2* p = (ulonglong2*)(Lr + f);
            ulonglong2 c = *p;
            c.x = add2(c.x, lg[f]);
            c.y = add2(c.y, lg[f + 1]);
            *p = c;
        }

        // ---- softmax without max-sub: e = exp2(lg) ----
        #pragma unroll
        for (int f = 0; f < GQ; ++f) {
            float a, bb; up2(lg[f], a, bb);
            lg[f] = pk2(ex2a(a), ex2a(bb));
        }
        u64 ss[16];
        #pragma unroll
        for (int i = 0; i < 16; ++i) ss[i] = add2(lg[2 * i], lg[2 * i + 1]);
        #pragma unroll
        for (int i = 0; i < 8; ++i)  ss[i] = add2(ss[2 * i], ss[2 * i + 1]);
        #pragma unroll
        for (int i = 0; i < 4; ++i)  ss[i] = add2(ss[2 * i], ss[2 * i + 1]);
        ss[0] = add2(add2(ss[0], ss[1]), add2(ss[2], ss[3]));
        float sum0, sum1; up2(ss[0], sum0, sum1);
        const u64 rn = pk2(rcpa(sum0), rcpa(sum1));

        // ---- normalize + accumulate attn sums ----
        u64* Ar = sA + g * 130 + sp * 32;
        #pragma unroll
        for (int f = 0; f < GQ; f += 2) {
            lg[f]     = mul2(lg[f],     rn);
            lg[f + 1] = mul2(lg[f + 1], rn);
            ulonglong2* p = (ulonglong2*)(Ar + f);
            ulonglong2 c = *p;
            c.x = add2(c.x, lg[f]);
            c.y = add2(c.y, lg[f + 1]);
            *p = c;
        }

        cp_wait0();              // V(h) arrived
        __syncthreads();         // all warps done with sK/sQ

        // prefetch next-h K (async) and Q (LDG->regs, STS after x-phase)
        if (h < NH - 1) {
            load_q_ldg(qA, qB, q + base + (size_t)(h + 1) * DK * SLEN, lane, warp);
            stage_async(sK, k + base + (size_t)(h + 1) * DK * SLEN, t);
            cp_commit();
        }

        // ---- x[g][d] = sum_f attn[f] * V[f][d] ----
        u64 xv[DK];
        {
            const float* vb0 = sV + 2 * sp;   // f = 0
            #pragma unroll
            for (int d = 0; d < DK; ++d)
                xv[d] = mul2(lg[0], *(const u64*)(vb0 + 8 * d));
            #pragma unroll
            for (int f = 1; f < GQ; ++f) {
                const float* vb = sV + f * 128 + 2 * sp;
                #pragma unroll
                for (int d = 0; d < DK; ++d)
                    xv[d] = fma2(lg[f], *(const u64*)(vb + 8 * d), xv[d]);
            }
        }

        // ---- store x: out[b][g*128 + h*16 + d][s0 + 2sp + {0,1}] ----
        float* xo = out + (((size_t)(b * GQ + g) * HDIM) + (size_t)h * DK) * SLEN
                        + (size_t)s0 + 2 * sp;
        #pragma unroll
        for (int d = 0; d < DK; ++d)
            *(u64*)(xo + (size_t)d * SLEN) = xv[d];

        // late STS of Q(h+1) (sQ free since the barrier above)
        if (h < NH - 1) sts_q(sQ, qA, qB, lane, warp);
    }

    // ---- writeout head means ----
    __syncthreads();
    const size_t AOFF = (size_t)B_SZ * GQ * HDIM * SLEN;       // 33554432
    const size_t LOFF = AOFF + (size_t)B_SZ * GQ * GQ * SLEN;  // 41943040
    const u64 cA = pk2(0.125f, 0.125f);
    const float lsc = 0.125f / L2E;                            // undo log2-domain
    const u64 cL = pk2(lsc, lsc);
    #pragma unroll
    for (int i = 0; i < 8; ++i) {
        int r  = t + NT * i;      // 0..1023
        int f  = r & 31;
        int gg = r >> 5;
        const u64* As = sA + gg * 130 + f;
        const u64* Ls = sL + gg * 130 + f;
        size_t o = ((size_t)(b * GQ + gg) * GQ + f) * SLEN + (size_t)s0;
        #pragma unroll
        for (int sp2 = 0; sp2 < 4; ++sp2) {
            *(u64*)(out + AOFF + o + 2 * sp2) = mul2(As[sp2 * 32], cA);
            *(u64*)(out + LOFF + o + 2 * sp2) = mul2(Ls[sp2 * 32], cL);
        }
    }
}

extern "C" void kernel_launch(void* const* d_in, const int* in_sizes, int n_in,
                              void* d_out, int out_size)
{
    const float* q = (const float*)d_in[0];
    const float* k = (const float*)d_in[1];
    const float* v = (const float*)d_in[2];
    float* out = (float*)d_out;

    cudaFuncSetAttribute(sdpa_group_kernel,
                         cudaFuncAttributeMaxDynamicSharedMemorySize, SM_BYTES);

    dim3 grid(SLEN / STILE, B_SZ);
    sdpa_group_kernel<<<grid, NT, SM_BYTES>>>(q, k, v, out);
}